// round 8
// baseline (speedup 1.0000x reference)
#include <cuda_runtime.h>
#include <cuda_fp16.h>
#include <stdint.h>

// ============================================================================
// B=1024, F=64, D=64.
//   layer: h'[o,d] = relu(b[o] + sum_{i,j} W[o,i*64+j] * x[i,d] * h[j,d])
//   out[b] = bfc + sum_o Wfc[o]*sum_d h1 + sum_o Wfc[64+o]*sum_d h2
//
// h-stationary HMMA (mma.sync m16n8k16 f16->f32), barrier-free mainloop:
//   per chunk i:  G = W_i @ h     (h fp16 B-fragments in registers, per layer)
//                 acc[o,d] += x[i,d] * G[o,d]   (exact fp32)
// fp16x2 on W only: G = Wh*hh + Wl*hh = W*hh exactly (W split error 2^-22);
// dropped term = W*(h - fp16(h)) ~ 2^-11 relative -> final rel_err ~2e-4.
// G is double-buffered across the i-loop: chunk i MMAs write G[i&1] while the
// x-scaling FFMAs consume G[(i-1)&1] -> no WAR stall on the tensor pipe.
// W pre-split + pre-arranged in mma-A fragment order; A-operands via coalesced
// L1-cached LDG.128, double-buffered in registers. No smem staging for W.
// CTA = 1 batch, 128 threads (2 mh x 2 nh, m32n32), 2 CTAs/SM.
// ============================================================================

#define HH_OFF   0            // h fp16 [j*144B], 64 rows = 9216
#define XS_OFF   9216         // x fp32 [i*68 + d] = 17408
#define POOL_OFF 26624
#define SMEM_TOTAL 26688

// W in fragment order: index ((c*2 + mh)*16 + q)*32 + lane, q = kk*4+half*2+m
// uint4 = 4 A-fragment regs for (chunk c, mh, kk, half, m). half0=hi, half1=lo.
__device__ __align__(16) uint4 g_Wf[131072];   // 2 MB

// ---------------------------------------------------------------------------
static __device__ __forceinline__ uint32_t s2u(const void* p) {
    uint32_t a;
    asm("{ .reg .u64 t; cvta.to.shared.u64 t, %1; cvt.u32.u64 %0, t; }"
        : "=r"(a) : "l"(p));
    return a;
}
static __device__ __forceinline__ uint32_t h2bits(__half2 h) {
    return *reinterpret_cast<uint32_t*>(&h);
}

#define LDSM4T(r, addr) \
    asm volatile("ldmatrix.sync.aligned.m8n8.x4.trans.shared.b16 {%0,%1,%2,%3}, [%4];" \
                 : "=r"((r)[0]), "=r"((r)[1]), "=r"((r)[2]), "=r"((r)[3]) \
                 : "r"(addr))
#define MMAH(c, a, b0, b1) \
    asm volatile("mma.sync.aligned.m16n8k16.row.col.f32.f16.f16.f32 " \
                 "{%0,%1,%2,%3},{%4,%5,%6,%7},{%8,%9},{%0,%1,%2,%3};" \
                 : "+f"((c)[0]), "+f"((c)[1]), "+f"((c)[2]), "+f"((c)[3]) \
                 : "r"((a)[0]), "r"((a)[1]), "r"((a)[2]), "r"((a)[3]), \
                   "r"(b0), "r"(b1))
#define MMAHZ(c, a, b0, b1) \
    asm volatile("mma.sync.aligned.m16n8k16.row.col.f32.f16.f16.f32 " \
                 "{%0,%1,%2,%3},{%4,%5,%6,%7},{%8,%9},{%10,%10,%10,%10};" \
                 : "=f"((c)[0]), "=f"((c)[1]), "=f"((c)[2]), "=f"((c)[3]) \
                 : "r"((a)[0]), "r"((a)[1]), "r"((a)[2]), "r"((a)[3]), \
                   "r"(b0), "r"(b1), "f"(0.0f))

// ---------------------------------------------------------------------------
// Prologue: W -> fp16 hi/lo in mma-A fragment order.
__global__ void CIN_52553219834054_wsplit(const float* __restrict__ W1,
                                          const float* __restrict__ W2) {
    const int idx = blockIdx.x * 256 + threadIdx.x;    // 0..131071
    const int c    = idx >> 10;
    const int rem  = idx & 1023;
    const int mh   = rem >> 9;
    const int rem2 = rem & 511;
    const int q    = rem2 >> 5;
    const int lane = rem2 & 31;
    const int kk = q >> 2, half = (q >> 1) & 1, m = q & 1;
    const int l = c >> 6, i = c & 63;
    const float* __restrict__ W = l ? W2 : W1;
    const int r = lane >> 2, tg = lane & 3;

    uint32_t regs[4];
    #pragma unroll
    for (int e = 0; e < 4; ++e) {
        const int row = mh * 32 + m * 16 + r + (e & 1) * 8;
        const int j   = kk * 16 + tg * 2 + (e >> 1) * 8;
        const float v0 = W[row * 4096 + i * 64 + j];
        const float v1 = W[row * 4096 + i * 64 + j + 1];
        const __half2 hp = __floats2half2_rn(v0, v1);   // .x = v0 (low bits)
        if (half == 0) {
            regs[e] = h2bits(hp);
        } else {
            const float2 bk = __half22float2(hp);
            regs[e] = h2bits(__floats2half2_rn(v0 - bk.x, v1 - bk.y));
        }
    }
    g_Wf[idx] = make_uint4(regs[0], regs[1], regs[2], regs[3]);
}

// ---------------------------------------------------------------------------
__global__ __launch_bounds__(128, 2) void CIN_52553219834054_kernel(
    const float* __restrict__ x,
    const float* __restrict__ b1, const float* __restrict__ b2,
    const float* __restrict__ Wfc, const float* __restrict__ bfc,
    float* __restrict__ out)
{
    extern __shared__ __align__(16) char smem[];
    const uint32_t sb = s2u(smem);
    const int tid = threadIdx.x, wid = tid >> 5, lane = tid & 31;
    const int mh = wid >> 1;          // m-half (rows mh*32..+31)
    const int nh = wid & 1;           // n-half (cols nh*32..+31)

    // ---- init: x -> XS fp32; h0 = fp16(x) ----
    {
        const float4* xg = (const float4*)(x + (size_t)blockIdx.x * 4096);
        float* XSf = (float*)(smem + XS_OFF);
        char* hb = smem + HH_OFF;
        #pragma unroll
        for (int t = 0; t < 8; ++t) {
            const int q = tid + t * 128;            // 0..1023
            const int i = q >> 4, d4 = (q & 15) * 4;
            const float4 v = xg[q];
            *(float4*)(XSf + i * 68 + d4) = v;
            *(uint2*)(hb + i * 144 + d4 * 2) =
                make_uint2(h2bits(__floats2half2_rn(v.x, v.y)),
                           h2bits(__floats2half2_rn(v.z, v.w)));
        }
    }
    __syncthreads();

    const int zl_lane = (lane & 15) * 144 + ((lane >> 4) << 4);
    const uint4* __restrict__ wfp = &g_Wf[mh * 512 + lane];  // + c*1024 + kk*128

    // A-fragment double buffer: [buf][0]=hi m0, [1]=hi m1, [2]=lo m0, [3]=lo m1
    uint4 A[2][4];
    {   // preload chunk 0, kk 0
        const uint4* p = wfp;
        A[0][0] = __ldg(p);      A[0][1] = __ldg(p + 32);
        A[0][2] = __ldg(p + 64); A[0][3] = __ldg(p + 96);
    }

    float pool = 0.0f;

    #pragma unroll 1
    for (int l = 0; l < 2; ++l) {
        // ---- h B-fragments (fp16) into registers, once per layer ----
        uint32_t Bh[4][2][4];
        {
            const uint32_t hbase = sb + HH_OFF;
            #pragma unroll
            for (int kk = 0; kk < 4; ++kk)
                #pragma unroll
                for (int g = 0; g < 2; ++g)
                    LDSM4T(Bh[kk][g],
                           hbase + zl_lane + kk * 2304 + (nh * 2 + g) * 32);
        }
        __syncthreads();   // all B-frags read before epilogue may rewrite h

        float acc[2][4][4];
        #pragma unroll
        for (int m = 0; m < 2; ++m)
            #pragma unroll
            for (int np = 0; np < 4; ++np)
                #pragma unroll
                for (int e = 0; e < 4; ++e) acc[m][np][e] = 0.0f;

        float G[2][2][4][4];   // ping-pong across i

        #pragma unroll 1
        for (int i = 0; i < 64; ++i) {
            const int c = l * 64 + i;
            const int cu = i & 1;

            #pragma unroll
            for (int kk = 0; kk < 4; ++kk) {
                // prefetch next (chunk, kk) A-fragments
                {
                    const int nkk = (kk + 1) & 3;
                    const int nc  = (kk == 3) ? c + 1 : c;
                    if (nc < 128) {
                        const uint4* p = wfp + nc * 1024 + nkk * 128;
                        uint4* dst = A[(kk + 1) & 1];
                        dst[0] = __ldg(p);      dst[1] = __ldg(p + 32);
                        dst[2] = __ldg(p + 64); dst[3] = __ldg(p + 96);
                    }
                }
                const uint32_t* Ah[2] = { (const uint32_t*)&A[kk & 1][0],
                                          (const uint32_t*)&A[kk & 1][1] };
                const uint32_t* Al[2] = { (const uint32_t*)&A[kk & 1][2],
                                          (const uint32_t*)&A[kk & 1][3] };
                #pragma unroll
                for (int m = 0; m < 2; ++m)
                    #pragma unroll
                    for (int np = 0; np < 4; ++np) {
                        const int g = np >> 1, pr = (np & 1) * 2;
                        const uint32_t b0 = Bh[kk][g][pr];
                        const uint32_t b1 = Bh[kk][g][pr + 1];
                        if (kk == 0) { MMAHZ(G[cu][m][np], Ah[m], b0, b1); }
                        else         { MMAH (G[cu][m][np], Ah[m], b0, b1); }
                        MMAH(G[cu][m][np], Al[m], b0, b1);
                    }
            }

            // apply x-scaling for the PREVIOUS chunk (independent G buffer)
            if (i > 0) {
                const int ip = i - 1, pu = cu ^ 1;
                const float* xrow = (const float*)(smem + XS_OFF)
                                  + ip * 68 + nh * 32 + (lane & 3) * 2;
                #pragma unroll
                for (int np = 0; np < 4; ++np) {
                    const float2 xv = *(const float2*)(xrow + np * 8);
                    #pragma unroll
                    for (int m = 0; m < 2; ++m) {
                        acc[m][np][0] += xv.x * G[pu][m][np][0];
                        acc[m][np][1] += xv.y * G[pu][m][np][1];
                        acc[m][np][2] += xv.x * G[pu][m][np][2];
                        acc[m][np][3] += xv.y * G[pu][m][np][3];
                    }
                }
            }
        }
        // flush last chunk (i = 63 -> buffer 1)
        {
            const float* xrow = (const float*)(smem + XS_OFF)
                              + 63 * 68 + nh * 32 + (lane & 3) * 2;
            #pragma unroll
            for (int np = 0; np < 4; ++np) {
                const float2 xv = *(const float2*)(xrow + np * 8);
                #pragma unroll
                for (int m = 0; m < 2; ++m) {
                    acc[m][np][0] += xv.x * G[1][m][np][0];
                    acc[m][np][1] += xv.y * G[1][m][np][1];
                    acc[m][np][2] += xv.x * G[1][m][np][2];
                    acc[m][np][3] += xv.y * G[1][m][np][3];
                }
            }
        }

        // ---- epilogue: bias + relu, pool, write next h (fp16) ----
        {
            const float* bg = l ? b2 : b1;
            const int d0 = nh * 32 + (lane & 3) * 2;
            char* hb = smem + HH_OFF;
            float ps = 0.0f;
            #pragma unroll
            for (int m = 0; m < 2; ++m) {
                const int o_lo = mh * 32 + m * 16 + (lane >> 2);
                const int o_hi = o_lo + 8;
                const float blv = bg[o_lo], bhv = bg[o_hi];
                const float wlv = Wfc[l * 64 + o_lo], whv = Wfc[l * 64 + o_hi];
                #pragma unroll
                for (int np = 0; np < 4; ++np) {
                    const int d = d0 + np * 8;
                    float v0 = fmaxf(acc[m][np][0] + blv, 0.0f);
                    float v1 = fmaxf(acc[m][np][1] + blv, 0.0f);
                    float v2 = fmaxf(acc[m][np][2] + bhv, 0.0f);
                    float v3 = fmaxf(acc[m][np][3] + bhv, 0.0f);
                    ps += wlv * (v0 + v1) + whv * (v2 + v3);
                    if (l == 0) {
                        *(uint32_t*)(hb + o_lo * 144 + d * 2) =
                            h2bits(__floats2half2_rn(v0, v1));
                        *(uint32_t*)(hb + o_hi * 144 + d * 2) =
                            h2bits(__floats2half2_rn(v2, v3));
                    }
                }
            }
            pool += ps;
        }
        __syncthreads();   // h visible before next-layer B-frag load
    }

    // ---- reduce pool across 4 warps, write out ----
    #pragma unroll
    for (int off = 16; off > 0; off >>= 1)
        pool += __shfl_xor_sync(0xffffffffu, pool, off);
    float* pb = (float*)(smem + POOL_OFF);
    if (lane == 0) pb[wid] = pool;
    __syncthreads();
    if (tid == 0)
        out[blockIdx.x] = pb[0] + pb[1] + pb[2] + pb[3] + bfc[0];
}

// ---------------------------------------------------------------------------
extern "C" void kernel_launch(void* const* d_in, const int* in_sizes, int n_in,
                              void* d_out, int out_size) {
    const float* x   = (const float*)d_in[0];
    const float* W1  = (const float*)d_in[1];
    const float* b1  = (const float*)d_in[2];
    const float* W2  = (const float*)d_in[3];
    const float* b2  = (const float*)d_in[4];
    const float* Wfc = (const float*)d_in[5];
    const float* bfc = (const float*)d_in[6];

    cudaFuncSetAttribute(CIN_52553219834054_kernel,
                         cudaFuncAttributeMaxDynamicSharedMemorySize, SMEM_TOTAL);

    CIN_52553219834054_wsplit<<<512, 256>>>(W1, W2);
    CIN_52553219834054_kernel<<<1024, 128, SMEM_TOTAL>>>(
        x, b1, b2, Wfc, bfc, (float*)d_out);
}

// round 9
// speedup vs baseline: 4.2205x; 4.2205x over previous
#include <cuda_runtime.h>
#include <cuda_fp16.h>
#include <stdint.h>

// ============================================================================
// B=1024, F=64, D=64.
//   layer: h'[o,d] = relu(b[o] + sum_{i,j} W[o,i*64+j] * x[i,d] * h[j,d])
//   out[b] = bfc + sum_o Wfc[o]*sum_d h1 + sum_o Wfc[64+o]*sum_d h2
//
// h-stationary HMMA (mma.sync m16n8k16 f16->f32), barrier-free mainloop:
//   per chunk i:  G = W_i @ h    (h fp16 B-fragments in registers, per layer)
//                 acc[o,d] += x[i,d] * G[o,d]   (exact fp32, immediately)
// fp16x2 on W only: G = Wh*hh + Wl*hh = W*hh exactly (W split exact to 2^-22);
// dropped term W*(h-fp16(h)) ~2^-11 rel -> measured rel_err 7e-5 (R8).
// NO G ping-pong (R8 lesson: +64 regs -> spill -> 2.7x regression).
// W pre-split + pre-arranged in mma-A fragment order; A-operands via coalesced
// L1-cached LDG.128, double-buffered in registers. No smem staging for W.
// CTA = 1 batch, 128 threads (2 mh x 2 nh, m32n32), 2 CTAs/SM.
// ============================================================================

#define HH_OFF   0            // h fp16 [j*144B], 64 rows = 9216
#define XS_OFF   9216         // x fp32 [i*68 + d] = 17408
#define POOL_OFF 26624
#define SMEM_TOTAL 26688

// W in fragment order: index ((c*2 + mh)*16 + q)*32 + lane, q = kk*4+half*2+m
// uint4 = 4 A-fragment regs for (chunk c, mh, kk, half, m). half0=hi, half1=lo.
__device__ __align__(16) uint4 g_Wf[131072];   // 2 MB

// ---------------------------------------------------------------------------
static __device__ __forceinline__ uint32_t s2u(const void* p) {
    uint32_t a;
    asm("{ .reg .u64 t; cvta.to.shared.u64 t, %1; cvt.u32.u64 %0, t; }"
        : "=r"(a) : "l"(p));
    return a;
}
static __device__ __forceinline__ uint32_t h2bits(__half2 h) {
    return *reinterpret_cast<uint32_t*>(&h);
}

#define LDSM4T(r, addr) \
    asm volatile("ldmatrix.sync.aligned.m8n8.x4.trans.shared.b16 {%0,%1,%2,%3}, [%4];" \
                 : "=r"((r)[0]), "=r"((r)[1]), "=r"((r)[2]), "=r"((r)[3]) \
                 : "r"(addr))
#define MMAH(c, a, b0, b1) \
    asm volatile("mma.sync.aligned.m16n8k16.row.col.f32.f16.f16.f32 " \
                 "{%0,%1,%2,%3},{%4,%5,%6,%7},{%8,%9},{%0,%1,%2,%3};" \
                 : "+f"((c)[0]), "+f"((c)[1]), "+f"((c)[2]), "+f"((c)[3]) \
                 : "r"((a)[0]), "r"((a)[1]), "r"((a)[2]), "r"((a)[3]), \
                   "r"(b0), "r"(b1))
#define MMAHZ(c, a, b0, b1) \
    asm volatile("mma.sync.aligned.m16n8k16.row.col.f32.f16.f16.f32 " \
                 "{%0,%1,%2,%3},{%4,%5,%6,%7},{%8,%9},{%10,%10,%10,%10};" \
                 : "=f"((c)[0]), "=f"((c)[1]), "=f"((c)[2]), "=f"((c)[3]) \
                 : "r"((a)[0]), "r"((a)[1]), "r"((a)[2]), "r"((a)[3]), \
                   "r"(b0), "r"(b1), "f"(0.0f))

// ---------------------------------------------------------------------------
// Prologue: W -> fp16 hi/lo in mma-A fragment order.
__global__ void CIN_52553219834054_wsplit(const float* __restrict__ W1,
                                          const float* __restrict__ W2) {
    const int idx = blockIdx.x * 256 + threadIdx.x;    // 0..131071
    const int c    = idx >> 10;
    const int rem  = idx & 1023;
    const int mh   = rem >> 9;
    const int rem2 = rem & 511;
    const int q    = rem2 >> 5;
    const int lane = rem2 & 31;
    const int kk = q >> 2, half = (q >> 1) & 1, m = q & 1;
    const int l = c >> 6, i = c & 63;
    const float* __restrict__ W = l ? W2 : W1;
    const int r = lane >> 2, tg = lane & 3;

    uint32_t regs[4];
    #pragma unroll
    for (int e = 0; e < 4; ++e) {
        const int row = mh * 32 + m * 16 + r + (e & 1) * 8;
        const int j   = kk * 16 + tg * 2 + (e >> 1) * 8;
        const float v0 = W[row * 4096 + i * 64 + j];
        const float v1 = W[row * 4096 + i * 64 + j + 1];
        const __half2 hp = __floats2half2_rn(v0, v1);   // .x = v0 (low bits)
        if (half == 0) {
            regs[e] = h2bits(hp);
        } else {
            const float2 bk = __half22float2(hp);
            regs[e] = h2bits(__floats2half2_rn(v0 - bk.x, v1 - bk.y));
        }
    }
    g_Wf[idx] = make_uint4(regs[0], regs[1], regs[2], regs[3]);
}

// ---------------------------------------------------------------------------
__global__ __launch_bounds__(128, 2) void CIN_52553219834054_kernel(
    const float* __restrict__ x,
    const float* __restrict__ b1, const float* __restrict__ b2,
    const float* __restrict__ Wfc, const float* __restrict__ bfc,
    float* __restrict__ out)
{
    extern __shared__ __align__(16) char smem[];
    const uint32_t sb = s2u(smem);
    const int tid = threadIdx.x, wid = tid >> 5, lane = tid & 31;
    const int mh = wid >> 1;          // m-half (rows mh*32..+31)
    const int nh = wid & 1;           // n-half (cols nh*32..+31)

    // ---- init: x -> XS fp32; h0 = fp16(x) ----
    {
        const float4* xg = (const float4*)(x + (size_t)blockIdx.x * 4096);
        float* XSf = (float*)(smem + XS_OFF);
        char* hb = smem + HH_OFF;
        #pragma unroll
        for (int t = 0; t < 8; ++t) {
            const int q = tid + t * 128;            // 0..1023
            const int i = q >> 4, d4 = (q & 15) * 4;
            const float4 v = xg[q];
            *(float4*)(XSf + i * 68 + d4) = v;
            *(uint2*)(hb + i * 144 + d4 * 2) =
                make_uint2(h2bits(__floats2half2_rn(v.x, v.y)),
                           h2bits(__floats2half2_rn(v.z, v.w)));
        }
    }
    __syncthreads();

    const int zl_lane = (lane & 15) * 144 + ((lane >> 4) << 4);
    const uint4* __restrict__ wfp = &g_Wf[mh * 512 + lane];  // + c*1024 + kk*128

    // A-fragment double buffer: [buf][0]=hi m0, [1]=hi m1, [2]=lo m0, [3]=lo m1
    uint4 A[2][4];
    {   // preload chunk 0, kk 0
        const uint4* p = wfp;
        A[0][0] = __ldg(p);      A[0][1] = __ldg(p + 32);
        A[0][2] = __ldg(p + 64); A[0][3] = __ldg(p + 96);
    }

    float pool = 0.0f;

    #pragma unroll 1
    for (int l = 0; l < 2; ++l) {
        // ---- h B-fragments (fp16) into registers, once per layer ----
        uint32_t Bh[4][2][4];
        {
            const uint32_t hbase = sb + HH_OFF;
            #pragma unroll
            for (int kk = 0; kk < 4; ++kk)
                #pragma unroll
                for (int g = 0; g < 2; ++g)
                    LDSM4T(Bh[kk][g],
                           hbase + zl_lane + kk * 2304 + (nh * 2 + g) * 32);
        }
        __syncthreads();   // all B-frags read before epilogue may rewrite h

        float acc[2][4][4];
        #pragma unroll
        for (int m = 0; m < 2; ++m)
            #pragma unroll
            for (int np = 0; np < 4; ++np)
                #pragma unroll
                for (int e = 0; e < 4; ++e) acc[m][np][e] = 0.0f;

        #pragma unroll 1
        for (int i = 0; i < 64; ++i) {
            const int c = l * 64 + i;
            float G[2][4][4];

            #pragma unroll
            for (int kk = 0; kk < 4; ++kk) {
                // prefetch next (chunk, kk) A-fragments
                {
                    const int nkk = (kk + 1) & 3;
                    const int nc  = (kk == 3) ? c + 1 : c;
                    if (nc < 128) {
                        const uint4* p = wfp + nc * 1024 + nkk * 128;
                        uint4* dst = A[(kk + 1) & 1];
                        dst[0] = __ldg(p);      dst[1] = __ldg(p + 32);
                        dst[2] = __ldg(p + 64); dst[3] = __ldg(p + 96);
                    }
                }
                const uint32_t* Ah[2] = { (const uint32_t*)&A[kk & 1][0],
                                          (const uint32_t*)&A[kk & 1][1] };
                const uint32_t* Al[2] = { (const uint32_t*)&A[kk & 1][2],
                                          (const uint32_t*)&A[kk & 1][3] };
                #pragma unroll
                for (int m = 0; m < 2; ++m)
                    #pragma unroll
                    for (int np = 0; np < 4; ++np) {
                        const int g = np >> 1, pr = (np & 1) * 2;
                        const uint32_t b0 = Bh[kk][g][pr];
                        const uint32_t b1 = Bh[kk][g][pr + 1];
                        if (kk == 0) { MMAHZ(G[m][np], Ah[m], b0, b1); }
                        else         { MMAH (G[m][np], Ah[m], b0, b1); }
                        MMAH(G[m][np], Al[m], b0, b1);
                    }
            }

            // acc += x[i,d] * G (exact fp32)
            const float* xrow = (const float*)(smem + XS_OFF)
                              + i * 68 + nh * 32 + (lane & 3) * 2;
            #pragma unroll
            for (int np = 0; np < 4; ++np) {
                const float2 xv = *(const float2*)(xrow + np * 8);
                #pragma unroll
                for (int m = 0; m < 2; ++m) {
                    acc[m][np][0] += xv.x * G[m][np][0];
                    acc[m][np][1] += xv.y * G[m][np][1];
                    acc[m][np][2] += xv.x * G[m][np][2];
                    acc[m][np][3] += xv.y * G[m][np][3];
                }
            }
        }

        // ---- epilogue: bias + relu, pool, write next h (fp16) ----
        {
            const float* bg = l ? b2 : b1;
            const int d0 = nh * 32 + (lane & 3) * 2;
            char* hb = smem + HH_OFF;
            float ps = 0.0f;
            #pragma unroll
            for (int m = 0; m < 2; ++m) {
                const int o_lo = mh * 32 + m * 16 + (lane >> 2);
                const int o_hi = o_lo + 8;
                const float blv = bg[o_lo], bhv = bg[o_hi];
                const float wlv = Wfc[l * 64 + o_lo], whv = Wfc[l * 64 + o_hi];
                #pragma unroll
                for (int np = 0; np < 4; ++np) {
                    const int d = d0 + np * 8;
                    float v0 = fmaxf(acc[m][np][0] + blv, 0.0f);
                    float v1 = fmaxf(acc[m][np][1] + blv, 0.0f);
                    float v2 = fmaxf(acc[m][np][2] + bhv, 0.0f);
                    float v3 = fmaxf(acc[m][np][3] + bhv, 0.0f);
                    ps += wlv * (v0 + v1) + whv * (v2 + v3);
                    if (l == 0) {
                        *(uint32_t*)(hb + o_lo * 144 + d * 2) =
                            h2bits(__floats2half2_rn(v0, v1));
                        *(uint32_t*)(hb + o_hi * 144 + d * 2) =
                            h2bits(__floats2half2_rn(v2, v3));
                    }
                }
            }
            pool += ps;
        }
        __syncthreads();   // h visible before next-layer B-frag load
    }

    // ---- reduce pool across 4 warps, write out ----
    #pragma unroll
    for (int off = 16; off > 0; off >>= 1)
        pool += __shfl_xor_sync(0xffffffffu, pool, off);
    float* pb = (float*)(smem + POOL_OFF);
    if (lane == 0) pb[wid] = pool;
    __syncthreads();
    if (tid == 0)
        out[blockIdx.x] = pb[0] + pb[1] + pb[2] + pb[3] + bfc[0];
}

// ---------------------------------------------------------------------------
extern "C" void kernel_launch(void* const* d_in, const int* in_sizes, int n_in,
                              void* d_out, int out_size) {
    const float* x   = (const float*)d_in[0];
    const float* W1  = (const float*)d_in[1];
    const float* b1  = (const float*)d_in[2];
    const float* W2  = (const float*)d_in[3];
    const float* b2  = (const float*)d_in[4];
    const float* Wfc = (const float*)d_in[5];
    const float* bfc = (const float*)d_in[6];

    cudaFuncSetAttribute(CIN_52553219834054_kernel,
                         cudaFuncAttributeMaxDynamicSharedMemorySize, SMEM_TOTAL);

    CIN_52553219834054_wsplit<<<512, 256>>>(W1, W2);
    CIN_52553219834054_kernel<<<1024, 128, SMEM_TOTAL>>>(
        x, b1, b2, Wfc, bfc, (float*)d_out);
}

// round 10
// speedup vs baseline: 5.8309x; 1.3816x over previous
#include <cuda_runtime.h>
#include <cuda_fp16.h>
#include <stdint.h>

// ============================================================================
// B=1024, F=64, D=64.
//   layer: h'[o,d] = relu(b[o] + sum_{i,j} W[o,i*64+j] * x[i,d] * h[j,d])
//   out[b] = bfc + sum_o Wfc[o]*sum_d h1 + sum_o Wfc[64+o]*sum_d h2
//
// h-stationary HMMA (mma.sync m16n8k16 f16->f32), barrier-free mainloop:
//   per chunk i:  G = fp16(W_i) @ fp16(h)   (h B-fragments in regs per layer)
//                 acc[o,d] += x[i,d] * G[o,d]   (exact fp32, immediately)
// Single-fp16 W AND h (R9 measured: h-only truncation -> 7.1e-5; W truncation
// adds an independent same-order term -> ~1.2e-4 total, ~7x under 1e-3).
// 32 MMAs per chunk per warp (half of R9). W pre-converted + pre-arranged in
// mma-A fragment order; A-operands via coalesced L1-cached LDG.128, double-
// buffered in registers. No smem staging for W, no mainloop barriers.
// CTA = 1 batch, 128 threads (2 mh x 2 nh, m32n32), 3 CTAs/SM for latency
// hiding (R8 lesson: hide MMA->FFMA dependency with occupancy, not registers).
// ============================================================================

#define HH_OFF   0            // h fp16 [j*144B], 64 rows = 9216
#define XS_OFF   9216         // x fp32 [i*68 + d] = 17408
#define POOL_OFF 26624
#define SMEM_TOTAL 26688

// W in fragment order: index ((c*2 + mh)*8 + q)*32 + lane, q = kk*2 + m
// uint4 = 4 A-fragment regs for (chunk c, mh, kk, m).
__device__ __align__(16) uint4 g_Wf[65536];   // 1 MB

// ---------------------------------------------------------------------------
static __device__ __forceinline__ uint32_t s2u(const void* p) {
    uint32_t a;
    asm("{ .reg .u64 t; cvta.to.shared.u64 t, %1; cvt.u32.u64 %0, t; }"
        : "=r"(a) : "l"(p));
    return a;
}
static __device__ __forceinline__ uint32_t h2bits(__half2 h) {
    return *reinterpret_cast<uint32_t*>(&h);
}

#define LDSM4T(r, addr) \
    asm volatile("ldmatrix.sync.aligned.m8n8.x4.trans.shared.b16 {%0,%1,%2,%3}, [%4];" \
                 : "=r"((r)[0]), "=r"((r)[1]), "=r"((r)[2]), "=r"((r)[3]) \
                 : "r"(addr))
#define MMAH(c, a, b0, b1) \
    asm volatile("mma.sync.aligned.m16n8k16.row.col.f32.f16.f16.f32 " \
                 "{%0,%1,%2,%3},{%4,%5,%6,%7},{%8,%9},{%0,%1,%2,%3};" \
                 : "+f"((c)[0]), "+f"((c)[1]), "+f"((c)[2]), "+f"((c)[3]) \
                 : "r"((a)[0]), "r"((a)[1]), "r"((a)[2]), "r"((a)[3]), \
                   "r"(b0), "r"(b1))
#define MMAHZ(c, a, b0, b1) \
    asm volatile("mma.sync.aligned.m16n8k16.row.col.f32.f16.f16.f32 " \
                 "{%0,%1,%2,%3},{%4,%5,%6,%7},{%8,%9},{%10,%10,%10,%10};" \
                 : "=f"((c)[0]), "=f"((c)[1]), "=f"((c)[2]), "=f"((c)[3]) \
                 : "r"((a)[0]), "r"((a)[1]), "r"((a)[2]), "r"((a)[3]), \
                   "r"(b0), "r"(b1), "f"(0.0f))

// ---------------------------------------------------------------------------
// Prologue: W -> fp16 in mma-A fragment order.
__global__ void CIN_52553219834054_wsplit(const float* __restrict__ W1,
                                          const float* __restrict__ W2) {
    const int idx = blockIdx.x * 256 + threadIdx.x;    // 0..65535
    const int c    = idx >> 9;
    const int rem  = idx & 511;
    const int mh   = rem >> 8;
    const int rem2 = rem & 255;
    const int q    = rem2 >> 5;
    const int lane = rem2 & 31;
    const int kk = q >> 1, m = q & 1;
    const int l = c >> 6, i = c & 63;
    const float* __restrict__ W = l ? W2 : W1;
    const int r = lane >> 2, tg = lane & 3;

    uint32_t regs[4];
    #pragma unroll
    for (int e = 0; e < 4; ++e) {
        const int row = mh * 32 + m * 16 + r + (e & 1) * 8;
        const int j   = kk * 16 + tg * 2 + (e >> 1) * 8;
        const float v0 = W[row * 4096 + i * 64 + j];
        const float v1 = W[row * 4096 + i * 64 + j + 1];
        regs[e] = h2bits(__floats2half2_rn(v0, v1));   // .x = v0 (low bits)
    }
    g_Wf[idx] = make_uint4(regs[0], regs[1], regs[2], regs[3]);
}

// ---------------------------------------------------------------------------
__global__ __launch_bounds__(128, 3) void CIN_52553219834054_kernel(
    const float* __restrict__ x,
    const float* __restrict__ b1, const float* __restrict__ b2,
    const float* __restrict__ Wfc, const float* __restrict__ bfc,
    float* __restrict__ out)
{
    extern __shared__ __align__(16) char smem[];
    const uint32_t sb = s2u(smem);
    const int tid = threadIdx.x, wid = tid >> 5, lane = tid & 31;
    const int mh = wid >> 1;          // m-half (rows mh*32..+31)
    const int nh = wid & 1;           // n-half (cols nh*32..+31)

    // ---- init: x -> XS fp32; h0 = fp16(x) ----
    {
        const float4* xg = (const float4*)(x + (size_t)blockIdx.x * 4096);
        float* XSf = (float*)(smem + XS_OFF);
        char* hb = smem + HH_OFF;
        #pragma unroll
        for (int t = 0; t < 8; ++t) {
            const int q = tid + t * 128;            // 0..1023
            const int i = q >> 4, d4 = (q & 15) * 4;
            const float4 v = xg[q];
            *(float4*)(XSf + i * 68 + d4) = v;
            *(uint2*)(hb + i * 144 + d4 * 2) =
                make_uint2(h2bits(__floats2half2_rn(v.x, v.y)),
                           h2bits(__floats2half2_rn(v.z, v.w)));
        }
    }
    __syncthreads();

    const int zl_lane = (lane & 15) * 144 + ((lane >> 4) << 4);
    const uint4* __restrict__ wfp = &g_Wf[mh * 256 + lane];  // + c*512 + kk*64

    // A-fragment double buffer: [buf][m]
    uint4 A[2][2];
    {   // preload chunk 0, kk 0
        A[0][0] = __ldg(wfp); A[0][1] = __ldg(wfp + 32);
    }

    float pool = 0.0f;

    #pragma unroll 1
    for (int l = 0; l < 2; ++l) {
        // ---- h B-fragments (fp16) into registers, once per layer ----
        uint32_t Bh[4][2][4];
        {
            const uint32_t hbase = sb + HH_OFF;
            #pragma unroll
            for (int kk = 0; kk < 4; ++kk)
                #pragma unroll
                for (int g = 0; g < 2; ++g)
                    LDSM4T(Bh[kk][g],
                           hbase + zl_lane + kk * 2304 + (nh * 2 + g) * 32);
        }
        __syncthreads();   // all B-frags read before epilogue may rewrite h

        float acc[2][4][4];
        #pragma unroll
        for (int m = 0; m < 2; ++m)
            #pragma unroll
            for (int np = 0; np < 4; ++np)
                #pragma unroll
                for (int e = 0; e < 4; ++e) acc[m][np][e] = 0.0f;

        #pragma unroll 1
        for (int i = 0; i < 64; ++i) {
            const int c = l * 64 + i;
            float G[2][4][4];

            #pragma unroll
            for (int kk = 0; kk < 4; ++kk) {
                // prefetch next (chunk, kk) A-fragments
                {
                    const int nkk = (kk + 1) & 3;
                    const int nc  = (kk == 3) ? c + 1 : c;
                    if (nc < 128) {
                        const uint4* p = wfp + nc * 512 + nkk * 64;
                        uint4* dst = A[(kk + 1) & 1];
                        dst[0] = __ldg(p); dst[1] = __ldg(p + 32);
                    }
                }
                const uint32_t* Ah[2] = { (const uint32_t*)&A[kk & 1][0],
                                          (const uint32_t*)&A[kk & 1][1] };
                #pragma unroll
                for (int m = 0; m < 2; ++m)
                    #pragma unroll
                    for (int np = 0; np < 4; ++np) {
                        const int g = np >> 1, pr = (np & 1) * 2;
                        const uint32_t b0 = Bh[kk][g][pr];
                        const uint32_t b1 = Bh[kk][g][pr + 1];
                        if (kk == 0) { MMAHZ(G[m][np], Ah[m], b0, b1); }
                        else         { MMAH (G[m][np], Ah[m], b0, b1); }
                    }
            }

            // acc += x[i,d] * G (exact fp32)
            const float* xrow = (const float*)(smem + XS_OFF)
                              + i * 68 + nh * 32 + (lane & 3) * 2;
            #pragma unroll
            for (int np = 0; np < 4; ++np) {
                const float2 xv = *(const float2*)(xrow + np * 8);
                #pragma unroll
                for (int m = 0; m < 2; ++m) {
                    acc[m][np][0] += xv.x * G[m][np][0];
                    acc[m][np][1] += xv.y * G[m][np][1];
                    acc[m][np][2] += xv.x * G[m][np][2];
                    acc[m][np][3] += xv.y * G[m][np][3];
                }
            }
        }

        // ---- epilogue: bias + relu, pool, write next h (fp16) ----
        {
            const float* bg = l ? b2 : b1;
            const int d0 = nh * 32 + (lane & 3) * 2;
            char* hb = smem + HH_OFF;
            float ps = 0.0f;
            #pragma unroll
            for (int m = 0; m < 2; ++m) {
                const int o_lo = mh * 32 + m * 16 + (lane >> 2);
                const int o_hi = o_lo + 8;
                const float blv = bg[o_lo], bhv = bg[o_hi];
                const float wlv = Wfc[l * 64 + o_lo], whv = Wfc[l * 64 + o_hi];
                #pragma unroll
                for (int np = 0; np < 4; ++np) {
                    const int d = d0 + np * 8;
                    float v0 = fmaxf(acc[m][np][0] + blv, 0.0f);
                    float v1 = fmaxf(acc[m][np][1] + blv, 0.0f);
                    float v2 = fmaxf(acc[m][np][2] + bhv, 0.0f);
                    float v3 = fmaxf(acc[m][np][3] + bhv, 0.0f);
                    ps += wlv * (v0 + v1) + whv * (v2 + v3);
                    if (l == 0) {
                        *(uint32_t*)(hb + o_lo * 144 + d * 2) =
                            h2bits(__floats2half2_rn(v0, v1));
                        *(uint32_t*)(hb + o_hi * 144 + d * 2) =
                            h2bits(__floats2half2_rn(v2, v3));
                    }
                }
            }
            pool += ps;
        }
        __syncthreads();   // h visible before next-layer B-frag load
    }

    // ---- reduce pool across 4 warps, write out ----
    #pragma unroll
    for (int off = 16; off > 0; off >>= 1)
        pool += __shfl_xor_sync(0xffffffffu, pool, off);
    float* pb = (float*)(smem + POOL_OFF);
    if (lane == 0) pb[wid] = pool;
    __syncthreads();
    if (tid == 0)
        out[blockIdx.x] = pb[0] + pb[1] + pb[2] + pb[3] + bfc[0];
}

// ---------------------------------------------------------------------------
extern "C" void kernel_launch(void* const* d_in, const int* in_sizes, int n_in,
                              void* d_out, int out_size) {
    const float* x   = (const float*)d_in[0];
    const float* W1  = (const float*)d_in[1];
    const float* b1  = (const float*)d_in[2];
    const float* W2  = (const float*)d_in[3];
    const float* b2  = (const float*)d_in[4];
    const float* Wfc = (const float*)d_in[5];
    const float* bfc = (const float*)d_in[6];

    cudaFuncSetAttribute(CIN_52553219834054_kernel,
                         cudaFuncAttributeMaxDynamicSharedMemorySize, SMEM_TOTAL);

    CIN_52553219834054_wsplit<<<256, 256>>>(W1, W2);
    CIN_52553219834054_kernel<<<1024, 128, SMEM_TOTAL>>>(
        x, b1, b2, Wfc, bfc, (float*)d_out);
}